// round 14
// baseline (speedup 1.0000x reference)
#include <cuda_runtime.h>
#include <cuda_bf16.h>
#include <cstdint>

// Embedding_78666620994160
// out[t, e] = (W[e, ids[t]] + b[e]) * sqrt(512)
// ids: [8*4096] int32, W: [512, 50257] f32, b: [512] f32 -> out [32768,512] f32
//
// v13: fixed-capacity bucket sort (NO histogram, NO scan, NO grid barrier):
//   K1: pos = atomicAdd(cnt[parity][bkt]); slot[bkt][pos] = (token,id,epoch).
//       Bucket fill ~ Binomial(mean 20.9, sigma 4.6); CAP=64 => overflow
//       P ~ 1e-20; inputs fixed => deterministic.
//   K2: per-bucket transposed gather; slot validity = epoch tag match.
//       Epoch bump is done by the LAST gather block to finish (ticket
//       counter + __syncthreads) => no reader race. g_epoch starts at 1 so
//       zero-init slots are never valid.

#define VOCAB    50257
#define EMB      512
#define N_TOKENS (8 * 4096)
#define BUCKET_SHIFT 5
#define NBUCKETS ((VOCAB >> BUCKET_SHIFT) + 1)   // 1571
#define CAP      64

#define E4Q      32          // float4 lanes per e-quarter
#define S4_PITCH 33
#define GATHER_BLOCKS (NBUCKETS * 4)             // 6284

__device__ int      g_cnt[2][NBUCKETS];      // parity ping-pong counters
__device__ int4     g_slots[NBUCKETS * CAP]; // (token, id, epoch, pad)
__device__ int      g_epoch = 1;             // starts at 1 (zero-init tags invalid)
__device__ unsigned g_done  = 0;             // monotonic gather arrival ticket

// ---- K1: scatter into fixed-capacity buckets (64 blocks x 512) ----
__global__ void __launch_bounds__(512, 4)
scatter_kernel(const int* __restrict__ ids)
{
    const int e0  = g_epoch;             // stable (bumped only at end of gather)
    const int par = e0 & 1;
    const int t   = blockIdx.x * 512 + threadIdx.x;
    const int id  = __ldg(&ids[t]);
    const int bkt = id >> BUCKET_SHIFT;
    int pos = atomicAdd(&g_cnt[par][bkt], 1);
    if (pos < CAP)
        g_slots[bkt * CAP + pos] = make_int4(t, id, e0, 0);
}

// ---- K2: per-bucket transposed gather + housekeeping ----
// grid = (1571, 4); blockDim = (64, 8). Block handles one bucket's <=64
// tokens x 32 float4 (one e-quarter). Warp = 32 slots of the same 32-id
// bucket -> W row gather spans <=4 32B sectors. Invalid slots predicated off.
__global__ void __launch_bounds__(512, 4)
emb_gather_bkt_kernel(const float* __restrict__ W,
                      const float* __restrict__ b,
                      float* __restrict__ out)
{
    const float SCALE = 22.62741699796952f; // sqrt(512)
    __shared__ float4 S4[CAP * S4_PITCH];

    const int e0  = g_epoch;                 // every thread reads before any bump
    const int bkt = blockIdx.x;

    // housekeeping: one block zeroes NEXT parity's counters (consumed by the
    // next launch's scatter; this launch's scatter is already done)
    if (bkt == 0 && blockIdx.y == 0) {
        int tid = threadIdx.y * 64 + threadIdx.x;
        for (int i = tid; i < NBUCKETS; i += 512)
            g_cnt[(e0 + 1) & 1][i] = 0;
    }

    const int t  = threadIdx.x;               // 0..63 slot
    const int ty = threadIdx.y;               // 0..7
    const int e4base = blockIdx.y * E4Q;      // e-quarter origin (float4 units)

    int4 sl = __ldg(&g_slots[bkt * CAP + t]);
    const bool valid = (sl.z == e0);
    const int  id    = sl.y;

    // Phase 1: gather 4 e4-slots per thread (predicated on valid)
    if (valid) {
        #pragma unroll
        for (int i = 0; i < 4; i++) {
            int e4l = ty + 8 * i;              // 0..31 local
            int e4g = e4base + e4l;
            float4 bv = __ldg((const float4*)b + e4g);
            const float* wp = W + (size_t)(4 * e4g) * VOCAB + id;
            float4 r;
            r.x = (__ldg(wp)                      + bv.x) * SCALE;
            r.y = (__ldg(wp + (size_t)VOCAB)      + bv.y) * SCALE;
            r.z = (__ldg(wp + (size_t)2 * VOCAB)  + bv.z) * SCALE;
            r.w = (__ldg(wp + (size_t)3 * VOCAB)  + bv.w) * SCALE;
            S4[t * S4_PITCH + e4l] = r;
        }
    }

    __syncthreads();

    // Phase 2: token-major coalesced float4 streaming stores
    const int tid = ty * 64 + t;               // 0..511
    const int tl  = tid >> 3;                  // 0..63 slot
    const int ey  = tid & 7;                   // 0..7
    int4 sl2 = __ldg(&g_slots[bkt * CAP + tl]);
    if (sl2.z == e0) {
        float4* outp = (float4*)out + (size_t)sl2.x * (EMB / 4) + e4base;
        #pragma unroll
        for (int i = 0; i < 4; i++) {
            int e4l = ey + 8 * i;
            __stcs(&outp[e4l], S4[tl * S4_PITCH + e4l]);
        }
    }

    // epoch bump: last block to arrive (all blocks have read e0 by then).
    __syncthreads();                           // all warps of this block past reads
    if (tid == 0) {
        unsigned old = atomicAdd(&g_done, 1u);
        if (old == (unsigned)e0 * GATHER_BLOCKS - 1u)   // e0 starts at 1
            g_epoch = e0 + 1;
    }
}

extern "C" void kernel_launch(void* const* d_in, const int* in_sizes, int n_in,
                              void* d_out, int out_size)
{
    const int*   ids = (const int*)d_in[0];    // [32768] int32
    const float* W   = (const float*)d_in[1];  // [512*50257]
    const float* b   = (const float*)d_in[2];  // [512]
    float*       out = (float*)d_out;          // [32768*512]

    scatter_kernel<<<N_TOKENS / 512, 512>>>(ids);

    dim3 block(64, 8, 1);
    dim3 grid(NBUCKETS, EMB / (4 * E4Q), 1);   // 1571 x 4
    emb_gather_bkt_kernel<<<grid, block>>>(W, b, out);
}

// round 15
// speedup vs baseline: 1.1245x; 1.1245x over previous
#include <cuda_runtime.h>
#include <cuda_bf16.h>
#include <cstdint>

// Embedding_78666620994160
// out[t, e] = (W[e, ids[t]] + b[e]) * sqrt(512)
// ids: [8*4096] int32, W: [512, 50257] f32, b: [512] f32 -> out [32768,512] f32
//
// v14: ONE launch. Blocks 0-63 run the exact-compaction sort (hist ->
// 64-block barrier -> redundant local scan -> slice-zero hist -> scatter);
// ALL 2048 blocks wait on the scatter-done counter, then run the proven v9
// transposed gather tile (static mapping, CLC-friendly). Epoch-monotonic
// counters everywhere => graph-replay safe, no resets.

#define VOCAB    50257
#define EMB      512
#define N_TOKENS (8 * 4096)
#define BUCKET_SHIFT 5
#define NBINS_PAD 2048

#define SORT_BLOCKS 64
#define TOK_PER_BLK 32
#define E4_PER_BLK  64
#define S4_PITCH    65
#define TOTAL_BLOCKS 2048          // 1024 x 2

__device__ int  g_hist[NBINS_PAD];   // zeroed at load; sort blocks re-zero slices
__device__ int  g_cnt[NBINS_PAD];    // monotonic per-bucket scatter counters
__device__ int2 g_sorted[N_TOKENS];  // (token, id) bucket-sorted
__device__ int  g_epoch = 0;
__device__ volatile int g_bar1 = 0;  // hist-done arrivals (sort blocks)
__device__ volatile int g_bar2 = 0;  // scan-read-done arrivals (sort blocks)
__device__ volatile int g_scat = 0;  // scatter-done arrivals (sort blocks)
__device__ unsigned     g_done = 0;  // gather completion ticket (all blocks)

__global__ void __launch_bounds__(512, 4)
emb_all_kernel(const int* __restrict__ ids,
               const float* __restrict__ W,
               const float* __restrict__ b,
               float* __restrict__ out)
{
    const float SCALE = 22.62741699796952f; // sqrt(512)
    __shared__ float4 S4[TOK_PER_BLK * S4_PITCH];
    __shared__ int    sb[NBINS_PAD];
    __shared__ int    wsum[16];

    const int tid = threadIdx.y * 32 + threadIdx.x;   // 0..511
    const int bid = blockIdx.y * 1024 + blockIdx.x;   // 0..2047
    const int e0  = g_epoch;                          // stable this launch

    // ================= sort (blocks 0..63) =================
    if (bid < SORT_BLOCKS) {
        const int lane = tid & 31, wid = tid >> 5;
        const int t  = bid * 512 + tid;
        const int id = __ldg(&ids[t]);

        // Phase A: histogram
        atomicAdd(&g_hist[id >> BUCKET_SHIFT], 1);

        // barrier 1 (sort blocks; all in wave 1)
        __threadfence();
        __syncthreads();
        if (tid == 0) {
            atomicAdd((int*)&g_bar1, 1);
            while (g_bar1 < e0 * SORT_BLOCKS + SORT_BLOCKS) __nanosleep(32);
        }
        __syncthreads();
        __threadfence();

        // Phase B: redundant local scan (4 bins/thread)
        const int base = tid * 4;
        int v0 = g_hist[base + 0];
        int v1 = g_hist[base + 1];
        int v2 = g_hist[base + 2];
        int v3 = g_hist[base + 3];
        int s  = v0 + v1 + v2 + v3;

        int x = s;
        #pragma unroll
        for (int off = 1; off < 32; off <<= 1) {
            int y = __shfl_up_sync(0xffffffffu, x, off);
            if (lane >= off) x += y;
        }
        if (lane == 31) wsum[wid] = x;
        __syncthreads();
        if (wid == 0 && lane < 16) {
            int w = wsum[lane];
            int xw = w;
            #pragma unroll
            for (int off = 1; off < 16; off <<= 1) {
                int y = __shfl_up_sync(0x0000ffffu, xw, off);
                if (lane >= off) xw += y;
            }
            wsum[lane] = xw - w;
        }
        __syncthreads();

        int run = wsum[wid] + (x - s);
        sb[base + 0] = run - e0 * v0;   run += v0;
        sb[base + 1] = run - e0 * v1;   run += v1;
        sb[base + 2] = run - e0 * v2;   run += v2;
        sb[base + 3] = run - e0 * v3;
        __syncthreads();

        // barrier 2: everyone finished READING hist -> safe to zero slices
        if (tid == 0) {
            atomicAdd((int*)&g_bar2, 1);
            while (g_bar2 < e0 * SORT_BLOCKS + SORT_BLOCKS) __nanosleep(32);
        }
        __syncthreads();
        if (tid < 32) g_hist[bid * 32 + tid] = 0;   // my 32-bin slice

        // Phase C: scatter my 512 tokens
        int bkt = id >> BUCKET_SHIFT;
        int pos = sb[bkt] + atomicAdd(&g_cnt[bkt], 1);
        __stcs(&g_sorted[pos], make_int2(t, id));

        __threadfence();
        __syncthreads();
        if (tid == 0) atomicAdd((int*)&g_scat, 1);
    }

    // ================= wait for scatter completion =================
    if (tid == 0) {
        while (g_scat < e0 * SORT_BLOCKS + SORT_BLOCKS) __nanosleep(64);
    }
    __syncthreads();
    __threadfence();

    // ================= transposed gather (v9 config) =================
    int t  = threadIdx.x;                        // 0..31 local token
    int ty = threadIdx.y;                        // 0..15
    int sp = blockIdx.x * TOK_PER_BLK + t;       // sorted position
    int e4base = blockIdx.y * E4_PER_BLK;        // global float4 offset

    int id = __ldg(&g_sorted[sp]).y;

    #pragma unroll
    for (int i = 0; i < 4; i++) {
        int e4l = ty + 16 * i;                   // 0..63 local
        int e4g = e4base + e4l;
        float4 bv = __ldg((const float4*)b + e4g);
        const float* wp = W + (size_t)(4 * e4g) * VOCAB + id;
        float4 r;
        r.x = (__ldg(wp)                      + bv.x) * SCALE;
        r.y = (__ldg(wp + (size_t)VOCAB)      + bv.y) * SCALE;
        r.z = (__ldg(wp + (size_t)2 * VOCAB)  + bv.z) * SCALE;
        r.w = (__ldg(wp + (size_t)3 * VOCAB)  + bv.w) * SCALE;
        S4[t * S4_PITCH + e4l] = r;
    }

    __syncthreads();

    int tl = tid >> 4;                           // 0..31 local token
    int ey = tid & 15;                           // 0..15
    int token = __ldg(&g_sorted[blockIdx.x * TOK_PER_BLK + tl]).x;
    float4* outp = (float4*)out + (size_t)token * (EMB / 4) + e4base;
    #pragma unroll
    for (int i = 0; i < 4; i++) {
        int e4l = ey + 16 * i;
        __stcs(&outp[e4l], S4[tl * S4_PITCH + e4l]);
    }

    // ================= epoch bump: last of all 2048 blocks =================
    __syncthreads();                             // all warps past their e0 reads
    if (tid == 0) {
        unsigned old = atomicAdd(&g_done, 1u);
        if (old == (unsigned)e0 * TOTAL_BLOCKS + (TOTAL_BLOCKS - 1u))
            g_epoch = e0 + 1;
    }
}

extern "C" void kernel_launch(void* const* d_in, const int* in_sizes, int n_in,
                              void* d_out, int out_size)
{
    const int*   ids = (const int*)d_in[0];    // [32768] int32
    const float* W   = (const float*)d_in[1];  // [512*50257]
    const float* b   = (const float*)d_in[2];  // [512]
    float*       out = (float*)d_out;          // [32768*512]

    dim3 block(32, 16, 1);
    dim3 grid(N_TOKENS / TOK_PER_BLK, EMB / (4 * E4_PER_BLK), 1);  // 1024 x 2
    emb_all_kernel<<<grid, block>>>(ids, W, b, out);
}